// round 9
// baseline (speedup 1.0000x reference)
#include <cuda_runtime.h>
#include <math.h>

// Problem shape (fixed by reference setup_inputs)
#define N_  8192
#define M_  4096
#define D_  784
#define BM  128
#define BN  128
#define BK  16
#define MTILES (M_/BN)   // 32
#define LOG_2PI 1.8378770664093453f

// Small scratch only (allocation-free per harness rules; ~2.1 MB total)
__device__ __align__(16) float g_invstd[D_]; // 1/std
__device__ float g_pmax[MTILES * N_];        // partial row max per m-tile
__device__ float g_psum[MTILES * N_];        // partial row sum-exp per m-tile
__device__ float g_logconst;                 // -0.5*D*log(2pi) - sum(log std)

// ---------------------------------------------------------------------------
// invstd + logconst
__global__ __launch_bounds__(256) void prep_const(const float* __restrict__ stdv) {
    int tid = threadIdx.x;
    float s = 0.f;
    for (int d = tid; d < D_; d += 256) {
        float sv = stdv[d];
        g_invstd[d] = 1.0f / sv;
        s += logf(sv);
    }
    __shared__ float red[256];
    red[tid] = s; __syncthreads();
    #pragma unroll
    for (int k = 128; k > 0; k >>= 1) {
        if (tid < k) red[tid] += red[tid + k];
        __syncthreads();
    }
    if (tid == 0) g_logconst = -0.5f * (float)D_ * LOG_2PI - red[0];
}

// ---------------------------------------------------------------------------
// Distance-form fused kernel: acc[i][j] = sum_d ((samples_nd - x_md)/std_d)^2
// over a 128x128 (n,m) tile; then per-row (max, sum-exp) partials of
// s = -0.5*acc via a transparent smem reduction. No norms, no shuffles.
// 256 threads, 8x8 micro-tile per thread, BK=16 (D=784=49*16 exactly).
__global__ __launch_bounds__(256) void dist_lse(const float* __restrict__ samples,
                                                const float* __restrict__ x) {
    __shared__ float As[BK][BM];
    __shared__ float Bs[BK][BN];
    __shared__ float red[BM][17];   // [row][tx], padded
    __shared__ float rmx[BM];

    const int tid = threadIdx.x;
    const int tx = tid & 15;       // 0..15 -> m direction
    const int ty = tid >> 4;       // 0..15 -> n direction
    const int bn = blockIdx.x;     // m tile index (0..31)
    const int bm = blockIdx.y;     // n tile index (0..63)

    const float* A = samples + (size_t)bm * BM * D_;
    const float* B = x       + (size_t)bn * BN * D_;

    float acc[8][8];
    #pragma unroll
    for (int i = 0; i < 8; i++)
        #pragma unroll
        for (int j = 0; j < 8; j++) acc[i][j] = 0.f;

    for (int k0 = 0; k0 < D_; k0 += BK) {
        // Stage A/B tiles (128x16 each) transposed into smem, scaled by invstd.
        #pragma unroll
        for (int t = 0; t < 2; t++) {
            int i = tid + t * 256;          // 0..511
            int r = i >> 2;                 // row within tile 0..127
            int cg = (i & 3) * 4;           // k-group 0,4,8,12
            float4 iv = *(const float4*)(g_invstd + k0 + cg);
            float4 av = *(const float4*)(A + (size_t)r * D_ + k0 + cg);
            As[cg + 0][r] = av.x * iv.x; As[cg + 1][r] = av.y * iv.y;
            As[cg + 2][r] = av.z * iv.z; As[cg + 3][r] = av.w * iv.w;
            float4 bv = *(const float4*)(B + (size_t)r * D_ + k0 + cg);
            Bs[cg + 0][r] = bv.x * iv.x; Bs[cg + 1][r] = bv.y * iv.y;
            Bs[cg + 2][r] = bv.z * iv.z; Bs[cg + 3][r] = bv.w * iv.w;
        }
        __syncthreads();

        #pragma unroll
        for (int k = 0; k < BK; k++) {
            float a[8], b[8];
            float4 a0 = *(const float4*)&As[k][ty * 8];
            float4 a1 = *(const float4*)&As[k][ty * 8 + 4];
            a[0]=a0.x; a[1]=a0.y; a[2]=a0.z; a[3]=a0.w;
            a[4]=a1.x; a[5]=a1.y; a[6]=a1.z; a[7]=a1.w;
            float4 b0 = *(const float4*)&Bs[k][tx * 8];
            float4 b1 = *(const float4*)&Bs[k][tx * 8 + 4];
            b[0]=b0.x; b[1]=b0.y; b[2]=b0.z; b[3]=b0.w;
            b[4]=b1.x; b[5]=b1.y; b[6]=b1.z; b[7]=b1.w;
            #pragma unroll
            for (int i = 0; i < 8; i++)
                #pragma unroll
                for (int j = 0; j < 8; j++) {
                    float d = a[i] - b[j];
                    acc[i][j] = fmaf(d, d, acc[i][j]);
                }
        }
        __syncthreads();
    }

    // ---- Epilogue (smem, shuffle-free) ----
    // Phase 1: per-thread row maxima of s = -0.5*acc over its 8 columns.
    #pragma unroll
    for (int i = 0; i < 8; i++) {
        float mloc = -0.5f * acc[i][0];
        #pragma unroll
        for (int j = 1; j < 8; j++) mloc = fmaxf(mloc, -0.5f * acc[i][j]);
        red[ty * 8 + i][tx] = mloc;
    }
    __syncthreads();
    if (tid < BM) {
        float rm = red[tid][0];
        #pragma unroll
        for (int c = 1; c < 16; c++) rm = fmaxf(rm, red[tid][c]);
        rmx[tid] = rm;
    }
    __syncthreads();
    // Phase 2: per-thread row sums of exp(s - rowmax).
    #pragma unroll
    for (int i = 0; i < 8; i++) {
        float rm = rmx[ty * 8 + i];
        float sloc = 0.f;
        #pragma unroll
        for (int j = 0; j < 8; j++)
            sloc += __expf(fmaf(-0.5f, acc[i][j], -rm));
        red[ty * 8 + i][tx] = sloc;
    }
    __syncthreads();
    if (tid < BM) {
        float s = 0.f;
        #pragma unroll
        for (int c = 0; c < 16; c++) s += red[tid][c];
        int row = bm * BM + tid;
        g_pmax[bn * N_ + row] = rmx[tid];
        g_psum[bn * N_ + row] = s;
    }
}

// ---------------------------------------------------------------------------
// Combine m-tile partials into final logsumexp per row.
__global__ __launch_bounds__(256) void finalize(float* __restrict__ out) {
    int n = blockIdx.x * blockDim.x + threadIdx.x;
    if (n >= N_) return;
    float gmax = -INFINITY, gsum = 0.f;
    for (int t = 0; t < MTILES; t++) {
        float mx = g_pmax[t * N_ + n];
        float sm = g_psum[t * N_ + n];
        if (mx > gmax) {
            gsum = gsum * __expf(gmax - mx) + sm;
            gmax = mx;
        } else {
            gsum += sm * __expf(mx - gmax);
        }
    }
    out[n] = gmax + logf(gsum) + g_logconst - logf((float)M_);
}

// ---------------------------------------------------------------------------
extern "C" void kernel_launch(void* const* d_in, const int* in_sizes, int n_in,
                              void* d_out, int out_size) {
    // Bind inputs by ELEMENT COUNT (sizes are unique):
    //   samples: 8192*784 = 6422528, x: 4096*784 = 3211264, std: 784
    const float* samples = nullptr;
    const float* x       = nullptr;
    const float* stdv    = nullptr;
    for (int i = 0; i < n_in; i++) {
        if      (in_sizes[i] == N_ * D_) samples = (const float*)d_in[i];
        else if (in_sizes[i] == M_ * D_) x       = (const float*)d_in[i];
        else if (in_sizes[i] == D_)      stdv    = (const float*)d_in[i];
    }
    if (!samples || !x || !stdv) {
        samples = (const float*)d_in[0];
        x       = (const float*)d_in[1];
        stdv    = (const float*)d_in[2];
    }
    float* out = (float*)d_out;
    (void)out_size;

    prep_const<<<1, 256>>>(stdv);
    dist_lse<<<dim3(M_ / BN, N_ / BM), 256>>>(samples, x);
    finalize<<<(N_ + 255) / 256, 256>>>(out);
}

// round 10
// speedup vs baseline: 1.3306x; 1.3306x over previous
#include <cuda_runtime.h>
#include <math.h>

// Problem shape (fixed by reference setup_inputs)
#define N_  8192
#define M_  4096
#define D_  784
#define BM  128
#define BN  128
#define BK  16
#define KK  (BK/2)       // 8 packed-k rows
#define MTILES (M_/BN)   // 32
#define LOG_2PI 1.8378770664093453f

typedef unsigned long long u64;

// Small scratch (allocation-free per harness rules; ~2.1 MB)
__device__ __align__(16) float g_invstd[D_]; // 1/std
__device__ float g_pmax[MTILES * N_];        // partial row max per m-tile
__device__ float g_psum[MTILES * N_];        // partial row sum-exp per m-tile
__device__ float g_logconst;                 // -0.5*D*log(2pi) - sum(log std)

// ---- packed f32x2 helpers (FFMA2: 2x fp32 throughput on sm_103a) ----------
__device__ __forceinline__ u64 fma2(u64 a, u64 b, u64 c) {
    u64 d;
    asm("fma.rn.f32x2 %0, %1, %2, %3;" : "=l"(d) : "l"(a), "l"(b), "l"(c));
    return d;
}
__device__ __forceinline__ u64 pack2(float lo, float hi) {
    u64 d;
    asm("mov.b64 %0, {%1, %2};" : "=l"(d) : "f"(lo), "f"(hi));
    return d;
}
__device__ __forceinline__ float2 unpack2(u64 v) {
    float2 r;
    asm("mov.b64 {%0, %1}, %2;" : "=f"(r.x), "=f"(r.y) : "l"(v));
    return r;
}

// ---------------------------------------------------------------------------
// invstd + logconst
__global__ __launch_bounds__(256) void prep_const(const float* __restrict__ stdv) {
    int tid = threadIdx.x;
    float s = 0.f;
    for (int d = tid; d < D_; d += 256) {
        float sv = stdv[d];
        g_invstd[d] = 1.0f / sv;
        s += logf(sv);
    }
    __shared__ float red[256];
    red[tid] = s; __syncthreads();
    #pragma unroll
    for (int k = 128; k > 0; k >>= 1) {
        if (tid < k) red[tid] += red[tid + k];
        __syncthreads();
    }
    if (tid == 0) g_logconst = -0.5f * (float)D_ * LOG_2PI - red[0];
}

// ---------------------------------------------------------------------------
// Fused dot-form kernel with k-packed f32x2 FMAs.
// s[n,m] = u.v - 0.5||u||^2 - 0.5||v||^2  (all accumulated in-tile),
// then per-row (max, sum-exp) partials via smem reduction.
// 256 threads, 8x8 micro-tile per thread; thread columns strided (tx + 16j)
// for conflict-free LDS.64 on the B tile.
__global__ __launch_bounds__(256, 1) void dot_lse(const float* __restrict__ samples,
                                                  const float* __restrict__ x) {
    __shared__ u64 As2[KK][BM + 1];   // +1: kill staging-store conflicts
    __shared__ u64 Bs2[KK][BN + 1];
    __shared__ float red[BM][17];     // [row][tx], padded
    __shared__ float rmx[BM];

    const int tid = threadIdx.x;
    const int tx = tid & 15;       // 0..15 -> m direction (cols tx + 16j)
    const int ty = tid >> 4;       // 0..15 -> n direction (rows ty*8 + i)
    const int bn = blockIdx.x;     // m tile index (0..31)
    const int bm = blockIdx.y;     // n tile index (0..63)

    const float* A = samples + (size_t)bm * BM * D_;
    const float* B = x       + (size_t)bn * BN * D_;

    u64 acc[8][8];
    u64 un2[8], vn2[8];
    #pragma unroll
    for (int i = 0; i < 8; i++) {
        un2[i] = 0ull; vn2[i] = 0ull;
        #pragma unroll
        for (int j = 0; j < 8; j++) acc[i][j] = 0ull;
    }

    for (int k0 = 0; k0 < D_; k0 += BK) {
        // Stage A/B tiles (128x16) as k-pairs (u64), scaled by invstd.
        #pragma unroll
        for (int t = 0; t < 2; t++) {
            int i = tid + t * 256;          // 0..511
            int r = i >> 2;                 // row within tile 0..127
            int cg = (i & 3) * 4;           // k-group 0,4,8,12
            int kk = cg >> 1;               // packed row 0,2,4,6
            float4 iv = *(const float4*)(g_invstd + k0 + cg);
            float4 av = *(const float4*)(A + (size_t)r * D_ + k0 + cg);
            As2[kk + 0][r] = pack2(av.x * iv.x, av.y * iv.y);
            As2[kk + 1][r] = pack2(av.z * iv.z, av.w * iv.w);
            float4 bv = *(const float4*)(B + (size_t)r * D_ + k0 + cg);
            Bs2[kk + 0][r] = pack2(bv.x * iv.x, bv.y * iv.y);
            Bs2[kk + 1][r] = pack2(bv.z * iv.z, bv.w * iv.w);
        }
        __syncthreads();

        #pragma unroll
        for (int kk = 0; kk < KK; kk++) {
            u64 a2[8], b2[8];
            #pragma unroll
            for (int i = 0; i < 8; i++) a2[i] = As2[kk][ty * 8 + i];   // broadcast
            #pragma unroll
            for (int j = 0; j < 8; j++) b2[j] = Bs2[kk][tx + 16 * j];  // conflict-free
            #pragma unroll
            for (int i = 0; i < 8; i++) un2[i] = fma2(a2[i], a2[i], un2[i]);
            #pragma unroll
            for (int j = 0; j < 8; j++) vn2[j] = fma2(b2[j], b2[j], vn2[j]);
            #pragma unroll
            for (int i = 0; i < 8; i++)
                #pragma unroll
                for (int j = 0; j < 8; j++)
                    acc[i][j] = fma2(a2[i], b2[j], acc[i][j]);
        }
        __syncthreads();
    }

    // ---- Epilogue ----
    float un[8], vn[8];
    #pragma unroll
    for (int i = 0; i < 8; i++) {
        float2 t = unpack2(un2[i]); un[i] = t.x + t.y;
        float2 w = unpack2(vn2[i]); vn[i] = w.x + w.y;
    }
    float s[8][8];
    #pragma unroll
    for (int i = 0; i < 8; i++)
        #pragma unroll
        for (int j = 0; j < 8; j++) {
            float2 t = unpack2(acc[i][j]);
            s[i][j] = (t.x + t.y) - 0.5f * un[i] - 0.5f * vn[j];
        }

    // Phase 1: per-thread row maxima over its 8 columns, then row-wide max.
    #pragma unroll
    for (int i = 0; i < 8; i++) {
        float mloc = s[i][0];
        #pragma unroll
        for (int j = 1; j < 8; j++) mloc = fmaxf(mloc, s[i][j]);
        red[ty * 8 + i][tx] = mloc;
    }
    __syncthreads();
    if (tid < BM) {
        float rm = red[tid][0];
        #pragma unroll
        for (int c = 1; c < 16; c++) rm = fmaxf(rm, red[tid][c]);
        rmx[tid] = rm;
    }
    __syncthreads();
    // Phase 2: per-thread row sums of exp(s - rowmax), then row-wide sum.
    #pragma unroll
    for (int i = 0; i < 8; i++) {
        float rm = rmx[ty * 8 + i];
        float sloc = 0.f;
        #pragma unroll
        for (int j = 0; j < 8; j++) sloc += __expf(s[i][j] - rm);
        red[ty * 8 + i][tx] = sloc;
    }
    __syncthreads();
    if (tid < BM) {
        float sm = 0.f;
        #pragma unroll
        for (int c = 0; c < 16; c++) sm += red[tid][c];
        int row = bm * BM + tid;
        g_pmax[bn * N_ + row] = rmx[tid];
        g_psum[bn * N_ + row] = sm;
    }
}

// ---------------------------------------------------------------------------
// Combine m-tile partials into final logsumexp per row.
__global__ __launch_bounds__(256) void finalize(float* __restrict__ out) {
    int n = blockIdx.x * blockDim.x + threadIdx.x;
    if (n >= N_) return;
    float gmax = -INFINITY, gsum = 0.f;
    for (int t = 0; t < MTILES; t++) {
        float mx = g_pmax[t * N_ + n];
        float sm = g_psum[t * N_ + n];
        if (mx > gmax) {
            gsum = gsum * __expf(gmax - mx) + sm;
            gmax = mx;
        } else {
            gsum += sm * __expf(mx - gmax);
        }
    }
    out[n] = gmax + logf(gsum) + g_logconst - logf((float)M_);
}

// ---------------------------------------------------------------------------
extern "C" void kernel_launch(void* const* d_in, const int* in_sizes, int n_in,
                              void* d_out, int out_size) {
    // Bind inputs by ELEMENT COUNT (sizes are unique):
    //   samples: 8192*784 = 6422528, x: 4096*784 = 3211264, std: 784
    const float* samples = nullptr;
    const float* x       = nullptr;
    const float* stdv    = nullptr;
    for (int i = 0; i < n_in; i++) {
        if      (in_sizes[i] == N_ * D_) samples = (const float*)d_in[i];
        else if (in_sizes[i] == M_ * D_) x       = (const float*)d_in[i];
        else if (in_sizes[i] == D_)      stdv    = (const float*)d_in[i];
    }
    if (!samples || !x || !stdv) {
        samples = (const float*)d_in[0];
        x       = (const float*)d_in[1];
        stdv    = (const float*)d_in[2];
    }
    float* out = (float*)d_out;
    (void)out_size;

    prep_const<<<1, 256>>>(stdv);
    dot_lse<<<dim3(M_ / BN, N_ / BM), 256>>>(samples, x);
    finalize<<<(N_ + 255) / 256, 256>>>(out);
}